// round 3
// baseline (speedup 1.0000x reference)
#include <cuda_runtime.h>
#include <cuda_bf16.h>
#include <cstdint>

#define IN_CH   128
#define OUT_CH  128
#define NDEG    81
#define NCPT    17
#define P_TOT   6561
#define XB_STRIDE (IN_CH * P_TOT)

#define WROW 136                 // padded k-row length in bf16 (272 bytes)
#define WBLK (128 * WROW)        // per-degree elems (17408 bf16 = 34816 B)

// Pre-interpolated, bf16 hi/lo split weights in the padded [o][k] smem image.
__device__ __align__(16) __nv_bfloat16 wA_hi[NDEG * WBLK];
__device__ __align__(16) __nv_bfloat16 wA_lo[NDEG * WBLK];

__device__ __forceinline__ unsigned smem_u32(const void* p) {
    unsigned a;
    asm("{ .reg .u64 t; cvta.to.shared.u64 t, %1; cvt.u32.u64 %0, t; }"
        : "=r"(a) : "l"(p));
    return a;
}

#define LDSM4(R, ADDR)                                                        \
    asm volatile("ldmatrix.sync.aligned.m8n8.x4.shared.b16 "                  \
                 "{%0,%1,%2,%3}, [%4];"                                       \
                 : "=r"((R)[0]), "=r"((R)[1]), "=r"((R)[2]), "=r"((R)[3])     \
                 : "r"(ADDR))

#define MMA16816(D, A, B0, B1)                                                \
    asm volatile("mma.sync.aligned.m16n8k16.row.col.f32.bf16.bf16.f32 "       \
                 "{%0,%1,%2,%3},{%4,%5,%6,%7},{%8,%9},{%0,%1,%2,%3};"         \
                 : "+f"((D)[0]), "+f"((D)[1]), "+f"((D)[2]), "+f"((D)[3])     \
                 : "r"((A)[0]), "r"((A)[1]), "r"((A)[2]), "r"((A)[3]),        \
                   "r"(B0), "r"(B1))

// ---------------------------------------------------------------------------
// Kernel 1 (fused interp + pack): per (degree, 32-o chunk), interpolate the 2
// relevant anchors and emit bf16 hi/lo into padded [o][WROW] layout.
// Anchor loads are strided but the whole weight tensor (556KB) is L2-resident.
// Stores are k-contiguous -> coalesced.
// ---------------------------------------------------------------------------
__global__ __launch_bounds__(256) void shconv_interp_pack(const float* __restrict__ w)
{
    const int l  = blockIdx.x;
    const int o0 = blockIdx.y * 32;
    int s; float t;
    if (l < 75) { s = l / 5; t = (float)(l - s * 5) * 0.2f; }
    else        { s = 15;    t = (float)(l - 75) * 0.2f; }

    __nv_bfloat16* dhi = wA_hi + l * WBLK;
    __nv_bfloat16* dlo = wA_lo + l * WBLK;

    for (int e = threadIdx.x; e < 32 * 128; e += 256) {
        const int k  = e & 127;          // input channel (K dim)
        const int o  = o0 + (e >> 7);
        const float* a = w + ((k * OUT_CH + o) * NCPT + s);
        const float v = (1.0f - t) * a[0] + t * a[1];
        const __nv_bfloat16 h  = __float2bfloat16_rn(v);
        const __nv_bfloat16 lo = __float2bfloat16_rn(v - __bfloat162float(h));
        dhi[o * WROW + k] = h;
        dlo[o * WROW + k] = lo;
    }
}

// ---------------------------------------------------------------------------
// Kernel 2: per-(degree, 64-col tile) bf16 HMMA GEMM.
//   D[128 o][64 c] = Whi*Xhi + Whi*Xlo + Wlo*Xhi   (fp32 accum)
// 8 warps, each computes a 32x32 warp tile via m16n8k16 mma.sync.
// smem: A_hi 34816 | A_lo 34816 | B_hi 17408 | B_lo 17408 | coloff 256
// 272B row stride -> conflict-free ldmatrix (row offsets mod 128B all distinct)
// ---------------------------------------------------------------------------
#define SM_AHI  0
#define SM_ALO  34816
#define SM_BHI  69632
#define SM_BLO  87040
#define SM_COL  104448
#define DSMEM   104704

__global__ __launch_bounds__(256) void shconv_mma(const float* __restrict__ x,
                                                  float* __restrict__ out)
{
    const int l = blockIdx.y;
    if ((int)blockIdx.x > (l >> 1)) return;     // ntiles = l/2 + 1

    extern __shared__ __align__(16) char sm[];
    int* coloff = (int*)(sm + SM_COL);

    const int tid  = threadIdx.x;
    const int lane = tid & 31;
    const int wid  = tid >> 5;

    const int span  = 2 * l + 1;
    const int ncols = 16 * span;
    const int c0    = blockIdx.x * 64;

    if (tid < 64) {
        int c  = c0 + tid;
        int cc = c < ncols ? c : ncols - 1;     // clamp padding to a valid col
        int b  = cc / span;
        coloff[tid] = b * XB_STRIDE + l * l + (cc - b * span);
    }
    __syncthreads();

    // --- stage W: byte-identical copy of padded hi/lo blocks (2x34816B) ---
    {
        const uint4* sh = (const uint4*)(wA_hi + l * WBLK);  // 2176 uint4
        const uint4* sl = (const uint4*)(wA_lo + l * WBLK);
        uint4* dh = (uint4*)(sm + SM_AHI);
        uint4* dl = (uint4*)(sm + SM_ALO);
#pragma unroll
        for (int j = 0; j < 8; j++) {
            int e = tid + 256 * j;
            dh[e] = sh[e];
            dl[e] = sl[e];
        }
        if (tid < 128) {
            dh[2048 + tid] = sh[2048 + tid];
            dl[2048 + tid] = sl[2048 + tid];
        }
    }

    // --- stage X: coalesced fp32 loads, bf16 hi/lo split, padded [c][k] ---
    {
        __nv_bfloat16* bh = (__nv_bfloat16*)(sm + SM_BHI);
        __nv_bfloat16* bl = (__nv_bfloat16*)(sm + SM_BLO);
#pragma unroll 8
        for (int j = 0; j < 32; j++) {
            const int e = tid + 256 * j;      // 64 c x 128 k, c inner
            const int c = e & 63;
            const int k = e >> 6;
            const float v = x[coloff[c] + k * P_TOT];
            const __nv_bfloat16 h  = __float2bfloat16_rn(v);
            const __nv_bfloat16 lo = __float2bfloat16_rn(v - __bfloat162float(h));
            bh[c * WROW + k] = h;
            bl[c * WROW + k] = lo;
        }
    }
    __syncthreads();

    // --- warp tiles: 4 (o) x 2 (c) ---
    const int m_base = (wid >> 1) * 32;
    const int n_base = (wid & 1) * 32;

    const unsigned sb = smem_u32(sm);
    // A lane address: row = m_base + (lane&15), kbyte = (lane>>4)*16
    const unsigned aoff = (unsigned)(m_base + (lane & 15)) * 272u + (unsigned)(lane >> 4) * 16u;
    const unsigned aH0 = sb + SM_AHI + aoff, aH1 = aH0 + 16u * 272u;
    const unsigned aL0 = sb + SM_ALO + aoff, aL1 = aL0 + 16u * 272u;
    // B lane address: row = n_base + (lane&7)+((lane>>4)<<3), kbyte = ((lane>>3)&1)*16
    const unsigned boff = (unsigned)(n_base + ((lane & 7) | ((lane >> 4) << 3))) * 272u
                        + (unsigned)((lane >> 3) & 1) * 16u;
    const unsigned bH0 = sb + SM_BHI + boff, bH1 = bH0 + 16u * 272u;
    const unsigned bL0 = sb + SM_BLO + boff, bL1 = bL0 + 16u * 272u;

    float acc[2][4][4];
#pragma unroll
    for (int mf = 0; mf < 2; mf++)
#pragma unroll
        for (int nq = 0; nq < 4; nq++)
#pragma unroll
            for (int j = 0; j < 4; j++) acc[mf][nq][j] = 0.0f;

#pragma unroll
    for (int ks = 0; ks < 8; ks++) {
        const unsigned ko = (unsigned)ks * 32u;
        unsigned ah[2][4], al[2][4], bhf[2][4], blf[2][4];
        LDSM4(ah[0], aH0 + ko);  LDSM4(ah[1], aH1 + ko);
        LDSM4(al[0], aL0 + ko);  LDSM4(al[1], aL1 + ko);
        LDSM4(bhf[0], bH0 + ko); LDSM4(bhf[1], bH1 + ko);
        LDSM4(blf[0], bL0 + ko); LDSM4(blf[1], bL1 + ko);
#pragma unroll
        for (int mf = 0; mf < 2; mf++) {
#pragma unroll
            for (int nq = 0; nq < 4; nq++) {
                const unsigned* bph = &bhf[nq >> 1][(nq & 1) * 2];
                const unsigned* bpl = &blf[nq >> 1][(nq & 1) * 2];
                MMA16816(acc[mf][nq], ah[mf], bph[0], bph[1]);  // Whi*Xhi
                MMA16816(acc[mf][nq], ah[mf], bpl[0], bpl[1]);  // Whi*Xlo
                MMA16816(acc[mf][nq], al[mf], bph[0], bph[1]);  // Wlo*Xhi
            }
        }
    }

    // --- epilogue: direct guarded stores (8 cols per row land in 1 sector) ---
#pragma unroll
    for (int mf = 0; mf < 2; mf++) {
#pragma unroll
        for (int nq = 0; nq < 4; nq++) {
            const int r  = m_base + mf * 16 + (lane >> 2);
            const int cc = n_base + nq * 8 + (lane & 3) * 2;
            if (c0 + cc < ncols) {
                const int off = coloff[cc];
                out[off + r * P_TOT]       = acc[mf][nq][0];
                out[off + (r + 8) * P_TOT] = acc[mf][nq][2];
            }
            if (c0 + cc + 1 < ncols) {
                const int off = coloff[cc + 1];
                out[off + r * P_TOT]       = acc[mf][nq][1];
                out[off + (r + 8) * P_TOT] = acc[mf][nq][3];
            }
        }
    }
}

extern "C" void kernel_launch(void* const* d_in, const int* in_sizes, int n_in,
                              void* d_out, int out_size)
{
    const float* x = (const float*)d_in[0];      // [16,128,6561]
    const float* w = (const float*)d_in[1];      // [128,128,17,1]
    float* out = (float*)d_out;                  // [16,128,6561]

    cudaFuncSetAttribute(shconv_mma,
                         cudaFuncAttributeMaxDynamicSharedMemorySize, DSMEM);

    dim3 pg(NDEG, 4);
    shconv_interp_pack<<<pg, 256>>>(w);

    dim3 grid(41, NDEG);
    shconv_mma<<<grid, 256, DSMEM>>>(x, out);
}

// round 4
// speedup vs baseline: 2.0034x; 2.0034x over previous
#include <cuda_runtime.h>
#include <cuda_bf16.h>
#include <cstdint>

#define IN_CH   128
#define OUT_CH  128
#define NDEG    81
#define NCPT    17
#define P_TOT   6561
#define XB_STRIDE (IN_CH * P_TOT)

#define WROW 136                 // padded k-row length in bf16 (272 bytes)
#define WBLK (128 * WROW)        // per-degree elems (34816 B)
#define NT   4                   // 64-col tiles per CTA

// Pre-interpolated, bf16 hi/lo split weights in the padded [o][k] smem image.
__device__ __align__(16) __nv_bfloat16 wA_hi[NDEG * WBLK];
__device__ __align__(16) __nv_bfloat16 wA_lo[NDEG * WBLK];

__device__ __forceinline__ unsigned smem_u32(const void* p) {
    unsigned a;
    asm("{ .reg .u64 t; cvta.to.shared.u64 t, %1; cvt.u32.u64 %0, t; }"
        : "=r"(a) : "l"(p));
    return a;
}

#define LDSM4(R, ADDR)                                                        \
    asm volatile("ldmatrix.sync.aligned.m8n8.x4.shared.b16 "                  \
                 "{%0,%1,%2,%3}, [%4];"                                       \
                 : "=r"((R)[0]), "=r"((R)[1]), "=r"((R)[2]), "=r"((R)[3])     \
                 : "r"(ADDR))

#define MMA16816(D, A, B0, B1)                                                \
    asm volatile("mma.sync.aligned.m16n8k16.row.col.f32.bf16.bf16.f32 "       \
                 "{%0,%1,%2,%3},{%4,%5,%6,%7},{%8,%9},{%0,%1,%2,%3};"         \
                 : "+f"((D)[0]), "+f"((D)[1]), "+f"((D)[2]), "+f"((D)[3])     \
                 : "r"((A)[0]), "r"((A)[1]), "r"((A)[2]), "r"((A)[3]),        \
                   "r"(B0), "r"(B1))

#define CPA16(DST, SRC)                                                       \
    asm volatile("cp.async.cg.shared.global [%0], [%1], 16;"                  \
                 :: "r"(DST), "l"(SRC))

// ---------------------------------------------------------------------------
// Kernel 1: interp + pack, each anchor read once.
// Block = (o, 32-k chunk). anch[kk][s] bank-stride 17 (odd) -> conflict-free.
// ---------------------------------------------------------------------------
__global__ __launch_bounds__(256) void shconv_interp_pack(const float* __restrict__ w)
{
    __shared__ float anch[32][NCPT];
    const int o  = blockIdx.x >> 2;
    const int k0 = (blockIdx.x & 3) * 32;

    for (int e = threadIdx.x; e < 32 * NCPT; e += 256) {
        const int kk = e / NCPT, s = e % NCPT;
        anch[kk][s] = w[((k0 + kk) * OUT_CH + o) * NCPT + s];
    }
    __syncthreads();

    for (int e = threadIdx.x; e < NDEG * 32; e += 256) {
        const int l  = e >> 5;
        const int kk = e & 31;
        int s; float t;
        if (l < 75) { s = l / 5; t = (float)(l - s * 5) * 0.2f; }
        else        { s = 15;    t = (float)(l - 75) * 0.2f; }
        const float v = (1.0f - t) * anch[kk][s] + t * anch[kk][s + 1];
        const __nv_bfloat16 h  = __float2bfloat16_rn(v);
        const __nv_bfloat16 lo = __float2bfloat16_rn(v - __bfloat162float(h));
        const int idx = l * WBLK + o * WROW + k0 + kk;
        wA_hi[idx] = h;
        wA_lo[idx] = lo;
    }
}

// ---------------------------------------------------------------------------
// Kernel 2: per-(degree, 4-tile chunk) pipelined bf16 HMMA GEMM.
//   D[128 o][64 c] = Whi*Xhi + Whi*Xlo + Wlo*Xhi   (fp32 accum)
// W cp.async'd once per CTA; X(t+1) LDG-prefetched into regs during MMA(t).
// smem: A_hi 34816 | A_lo 34816 | B_hi 17408 | B_lo 17408 | coloff[2][64]
// ---------------------------------------------------------------------------
#define SM_AHI  0
#define SM_ALO  34816
#define SM_BHI  69632
#define SM_BLO  87040
#define SM_COL  104448
#define DSMEM   104960

__global__ __launch_bounds__(256, 2) void shconv_mma(const float* __restrict__ x,
                                                     float* __restrict__ out)
{
    const int l      = blockIdx.y;
    const int ntiles = (l >> 1) + 1;
    const int t0     = blockIdx.x * NT;
    int nt = ntiles - t0;
    if (nt <= 0) return;
    if (nt > NT) nt = NT;

    extern __shared__ __align__(16) char sm[];
    int* coloff = (int*)(sm + SM_COL);
    const unsigned sb = smem_u32(sm);

    const int tid  = threadIdx.x;
    const int lane = tid & 31;
    const int wid  = tid >> 5;
    const int span  = 2 * l + 1;
    const int ncols = 16 * span;

    // --- W: cp.async both hi/lo blocks (2x2176 uint4) ---
    {
        const char* gh = (const char*)(wA_hi + l * WBLK);
        const char* gl = (const char*)(wA_lo + l * WBLK);
#pragma unroll
        for (int j = 0; j < 9; j++) {
            const int e = tid + 256 * j;
            if (e < 2176) {
                CPA16(sb + SM_AHI + e * 16, gh + e * 16);
                CPA16(sb + SM_ALO + e * 16, gl + e * 16);
            }
        }
        asm volatile("cp.async.commit_group;" ::: "memory");
    }

    // --- coloff for tile 0 (buffer 0) ---
    if (tid < 64) {
        const int c  = t0 * 64 + tid;
        const int cc = c < ncols ? c : ncols - 1;
        const int b  = cc / span;
        coloff[tid] = b * XB_STRIDE + l * l + (cc - b * span);
    }
    __syncthreads();

    // --- prefetch X(tile 0): thread owns column xc, k = kb + {0,1} + 8j ---
    const int xc = tid & 63;
    const int kb = (tid >> 6) * 2;
    float xr[32];
    {
        const float* xp = x + coloff[xc];
#pragma unroll
        for (int j = 0; j < 16; j++) {
            xr[2 * j]     = xp[(kb + 8 * j) * P_TOT];
            xr[2 * j + 1] = xp[(kb + 8 * j + 1) * P_TOT];
        }
    }
    asm volatile("cp.async.wait_group 0;" ::: "memory");

    // --- fragment addresses (same geometry as validated round-3 kernel) ---
    const int m_base = (wid >> 1) * 32;
    const int n_base = (wid & 1) * 32;
    const unsigned aoff = (unsigned)(m_base + (lane & 15)) * 272u + (unsigned)(lane >> 4) * 16u;
    const unsigned aH0 = sb + SM_AHI + aoff, aH1 = aH0 + 16u * 272u;
    const unsigned aL0 = sb + SM_ALO + aoff, aL1 = aL0 + 16u * 272u;
    const unsigned boff = (unsigned)(n_base + ((lane & 7) | ((lane >> 4) << 3))) * 272u
                        + (unsigned)((lane >> 3) & 1) * 16u;
    const unsigned bH0 = sb + SM_BHI + boff, bH1 = bH0 + 16u * 272u;
    const unsigned bL0 = sb + SM_BLO + boff, bL1 = bL0 + 16u * 272u;

    char* bhp = sm + SM_BHI;
    char* blp = sm + SM_BLO;

    for (int tt = 0; tt < nt; tt++) {
        const int cur = tt & 1;

        // --- convert prefetched X -> bf16 hi/lo STS (paired 4B stores) ---
#pragma unroll
        for (int j = 0; j < 16; j++) {
            const float v0 = xr[2 * j], v1 = xr[2 * j + 1];
            const __nv_bfloat16 h0 = __float2bfloat16_rn(v0);
            const __nv_bfloat16 h1 = __float2bfloat16_rn(v1);
            const __nv_bfloat16 l0 = __float2bfloat16_rn(v0 - __bfloat162float(h0));
            const __nv_bfloat16 l1 = __float2bfloat16_rn(v1 - __bfloat162float(h1));
            const int k = kb + 8 * j;
            const unsigned hw = ((unsigned)__bfloat16_as_ushort(h1) << 16) | __bfloat16_as_ushort(h0);
            const unsigned lw = ((unsigned)__bfloat16_as_ushort(l1) << 16) | __bfloat16_as_ushort(l0);
            *(unsigned*)(bhp + xc * 272 + k * 2) = hw;
            *(unsigned*)(blp + xc * 272 + k * 2) = lw;
        }
        // coloff for next tile into the other buffer
        if (tt + 1 < nt && tid < 64) {
            const int c  = (t0 + tt + 1) * 64 + tid;
            const int cc = c < ncols ? c : ncols - 1;
            const int b  = cc / span;
            coloff[(cur ^ 1) * 64 + tid] = b * XB_STRIDE + l * l + (cc - b * span);
        }
        __syncthreads();

        // --- prefetch X(t+1) into regs (overlaps the MMA below) ---
        if (tt + 1 < nt) {
            const float* xp = x + coloff[(cur ^ 1) * 64 + xc];
#pragma unroll
            for (int j = 0; j < 16; j++) {
                xr[2 * j]     = xp[(kb + 8 * j) * P_TOT];
                xr[2 * j + 1] = xp[(kb + 8 * j + 1) * P_TOT];
            }
        }

        // --- MMA: 8 k-steps x (2 mf x 4 nq x 3 terms) ---
        float acc[2][4][4];
#pragma unroll
        for (int mf = 0; mf < 2; mf++)
#pragma unroll
            for (int nq = 0; nq < 4; nq++)
#pragma unroll
                for (int j = 0; j < 4; j++) acc[mf][nq][j] = 0.0f;

#pragma unroll
        for (int ks = 0; ks < 8; ks++) {
            const unsigned ko = (unsigned)ks * 32u;
            unsigned ah[2][4], al[2][4], bhf[2][4], blf[2][4];
            LDSM4(ah[0], aH0 + ko);  LDSM4(ah[1], aH1 + ko);
            LDSM4(al[0], aL0 + ko);  LDSM4(al[1], aL1 + ko);
            LDSM4(bhf[0], bH0 + ko); LDSM4(bhf[1], bH1 + ko);
            LDSM4(blf[0], bL0 + ko); LDSM4(blf[1], bL1 + ko);
#pragma unroll
            for (int mf = 0; mf < 2; mf++) {
#pragma unroll
                for (int nq = 0; nq < 4; nq++) {
                    const unsigned* bph = &bhf[nq >> 1][(nq & 1) * 2];
                    const unsigned* bpl = &blf[nq >> 1][(nq & 1) * 2];
                    MMA16816(acc[mf][nq], ah[mf], bph[0], bph[1]);  // Whi*Xhi
                    MMA16816(acc[mf][nq], ah[mf], bpl[0], bpl[1]);  // Whi*Xlo
                    MMA16816(acc[mf][nq], al[mf], bph[0], bph[1]);  // Wlo*Xhi
                }
            }
        }

        // --- epilogue: guarded direct stores ---
        const int c0t = (t0 + tt) * 64;
#pragma unroll
        for (int mf = 0; mf < 2; mf++) {
#pragma unroll
            for (int nq = 0; nq < 4; nq++) {
                const int r  = m_base + mf * 16 + (lane >> 2);
                const int cc = n_base + nq * 8 + (lane & 3) * 2;
                if (c0t + cc < ncols) {
                    const int off = coloff[cur * 64 + cc];
                    out[off + r * P_TOT]       = acc[mf][nq][0];
                    out[off + (r + 8) * P_TOT] = acc[mf][nq][2];
                }
                if (c0t + cc + 1 < ncols) {
                    const int off = coloff[cur * 64 + cc + 1];
                    out[off + r * P_TOT]       = acc[mf][nq][1];
                    out[off + (r + 8) * P_TOT] = acc[mf][nq][3];
                }
            }
        }
        __syncthreads();   // X smem + coloff[cur] safe to overwrite
    }
}

extern "C" void kernel_launch(void* const* d_in, const int* in_sizes, int n_in,
                              void* d_out, int out_size)
{
    const float* x = (const float*)d_in[0];      // [16,128,6561]
    const float* w = (const float*)d_in[1];      // [128,128,17,1]
    float* out = (float*)d_out;                  // [16,128,6561]

    cudaFuncSetAttribute(shconv_mma,
                         cudaFuncAttributeMaxDynamicSharedMemorySize, DSMEM);

    shconv_interp_pack<<<512, 256>>>(w);

    dim3 grid(11, NDEG);                         // 4-tile chunks x degrees
    shconv_mma<<<grid, 256, DSMEM>>>(x, out);
}

// round 5
// speedup vs baseline: 2.2216x; 1.1089x over previous
#include <cuda_runtime.h>
#include <cuda_bf16.h>
#include <cstdint>

#define IN_CH   128
#define OUT_CH  128
#define NDEG    81
#define NCPT    17
#define P_TOT   6561
#define XB_STRIDE (IN_CH * P_TOT)

#define WROW 136                 // padded k-row length in bf16 (272 bytes)
#define WBLK (128 * WROW)        // per-degree elems (34816 B)
#define NT   2                   // 64-col tiles per CTA

__device__ __align__(16) __nv_bfloat16 wA_hi[NDEG * WBLK];
__device__ __align__(16) __nv_bfloat16 wA_lo[NDEG * WBLK];

__device__ __forceinline__ unsigned smem_u32(const void* p) {
    unsigned a;
    asm("{ .reg .u64 t; cvta.to.shared.u64 t, %1; cvt.u32.u64 %0, t; }"
        : "=r"(a) : "l"(p));
    return a;
}

#define LDSM4(R, ADDR)                                                        \
    asm volatile("ldmatrix.sync.aligned.m8n8.x4.shared.b16 "                  \
                 "{%0,%1,%2,%3}, [%4];"                                       \
                 : "=r"((R)[0]), "=r"((R)[1]), "=r"((R)[2]), "=r"((R)[3])     \
                 : "r"(ADDR))

#define MMA16816(D, A, B0, B1)                                                \
    asm volatile("mma.sync.aligned.m16n8k16.row.col.f32.bf16.bf16.f32 "       \
                 "{%0,%1,%2,%3},{%4,%5,%6,%7},{%8,%9},{%0,%1,%2,%3};"         \
                 : "+f"((D)[0]), "+f"((D)[1]), "+f"((D)[2]), "+f"((D)[3])     \
                 : "r"((A)[0]), "r"((A)[1]), "r"((A)[2]), "r"((A)[3]),        \
                   "r"(B0), "r"(B1))

#define CPA16(DST, SRC)                                                       \
    asm volatile("cp.async.cg.shared.global [%0], [%1], 16;"                  \
                 :: "r"(DST), "l"(SRC))

// ---------------------------------------------------------------------------
// Kernel 1: interp + pack (unchanged from round 4 — each anchor read once).
// ---------------------------------------------------------------------------
__global__ __launch_bounds__(256) void shconv_interp_pack(const float* __restrict__ w)
{
    __shared__ float anch[32][NCPT];
    const int o  = blockIdx.x >> 2;
    const int k0 = (blockIdx.x & 3) * 32;

    for (int e = threadIdx.x; e < 32 * NCPT; e += 256) {
        const int kk = e / NCPT, s = e % NCPT;
        anch[kk][s] = w[((k0 + kk) * OUT_CH + o) * NCPT + s];
    }
    __syncthreads();

    for (int e = threadIdx.x; e < NDEG * 32; e += 256) {
        const int l  = e >> 5;
        const int kk = e & 31;
        int s; float t;
        if (l < 75) { s = l / 5; t = (float)(l - s * 5) * 0.2f; }
        else        { s = 15;    t = (float)(l - 75) * 0.2f; }
        const float v = (1.0f - t) * anch[kk][s] + t * anch[kk][s + 1];
        const __nv_bfloat16 h  = __float2bfloat16_rn(v);
        const __nv_bfloat16 lo = __float2bfloat16_rn(v - __bfloat162float(h));
        const int idx = l * WBLK + o * WROW + k0 + kk;
        wA_hi[idx] = h;
        wA_lo[idx] = lo;
    }
}

// ---------------------------------------------------------------------------
// Kernel 2: 512-thread, 16-warp pipelined bf16 HMMA GEMM, warp-tile 16x32.
//   D[128 o][64 c] = Whi*Xhi + Whi*Xlo + Wlo*Xhi   (fp32 accum)
// smem: A_hi 34816 | A_lo 34816 | B_hi 17408 | B_lo 17408 | coloff[2][64]
// ---------------------------------------------------------------------------
#define SM_AHI  0
#define SM_ALO  34816
#define SM_BHI  69632
#define SM_BLO  87040
#define SM_COL  104448
#define DSMEM   104960

__global__ __launch_bounds__(512, 2) void shconv_mma(const float* __restrict__ x,
                                                     float* __restrict__ out)
{
    const int l      = 80 - blockIdx.y;          // LPT: big degrees first
    const int ntiles = (l >> 1) + 1;
    const int t0     = blockIdx.x * NT;
    int nt = ntiles - t0;
    if (nt <= 0) return;
    if (nt > NT) nt = NT;

    extern __shared__ __align__(16) char sm[];
    int* coloff = (int*)(sm + SM_COL);
    const unsigned sb = smem_u32(sm);

    const int tid  = threadIdx.x;
    const int lane = tid & 31;
    const int wid  = tid >> 5;
    const int span  = 2 * l + 1;
    const int ncols = 16 * span;

    // --- W: cp.async both hi/lo blocks (2x2176 uint4) ---
    {
        const char* gh = (const char*)(wA_hi + l * WBLK);
        const char* gl = (const char*)(wA_lo + l * WBLK);
#pragma unroll
        for (int j = 0; j < 5; j++) {
            const int e = tid + 512 * j;
            if (e < 2176) {
                CPA16(sb + SM_AHI + e * 16, gh + e * 16);
                CPA16(sb + SM_ALO + e * 16, gl + e * 16);
            }
        }
        asm volatile("cp.async.commit_group;" ::: "memory");
    }

    // --- coloff for tile 0 (buffer 0) ---
    if (tid < 64) {
        const int c  = t0 * 64 + tid;
        const int cc = c < ncols ? c : ncols - 1;
        const int b  = cc / span;
        coloff[tid] = b * XB_STRIDE + l * l + (cc - b * span);
    }
    __syncthreads();

    // --- X ownership: thread -> (col xc, k in [kb, kb+16)), eager bf16 split ---
    const int xc = tid & 63;
    const int kb = (tid >> 6) * 16;
    unsigned xh[8], xl[8];
    {
        const float* xp = x + coloff[xc];
#pragma unroll
        for (int m = 0; m < 8; m++) {
            const float v0 = xp[(kb + 2 * m) * P_TOT];
            const float v1 = xp[(kb + 2 * m + 1) * P_TOT];
            const __nv_bfloat16 h0 = __float2bfloat16_rn(v0);
            const __nv_bfloat16 h1 = __float2bfloat16_rn(v1);
            const __nv_bfloat16 l0 = __float2bfloat16_rn(v0 - __bfloat162float(h0));
            const __nv_bfloat16 l1 = __float2bfloat16_rn(v1 - __bfloat162float(h1));
            xh[m] = ((unsigned)__bfloat16_as_ushort(h1) << 16) | __bfloat16_as_ushort(h0);
            xl[m] = ((unsigned)__bfloat16_as_ushort(l1) << 16) | __bfloat16_as_ushort(l0);
        }
    }
    asm volatile("cp.async.wait_group 0;" ::: "memory");

    // --- fragment addresses: warp-tile 16 (m) x 32 (n) ---
    const int m_base = (wid >> 1) * 16;
    const int n_base = (wid & 1) * 32;
    const unsigned aoff = (unsigned)(m_base + (lane & 15)) * 272u + (unsigned)(lane >> 4) * 16u;
    const unsigned aH0 = sb + SM_AHI + aoff;
    const unsigned aL0 = sb + SM_ALO + aoff;
    const unsigned boff = (unsigned)(n_base + ((lane & 7) | ((lane >> 4) << 3))) * 272u
                        + (unsigned)((lane >> 3) & 1) * 16u;
    const unsigned bH0 = sb + SM_BHI + boff, bH1 = bH0 + 16u * 272u;
    const unsigned bL0 = sb + SM_BLO + boff, bL1 = bL0 + 16u * 272u;

    char* bhp = sm + SM_BHI;
    char* blp = sm + SM_BLO;

    for (int tt = 0; tt < nt; tt++) {
        const int cur = tt & 1;

        // --- STS prefetched bf16 pairs ---
#pragma unroll
        for (int m = 0; m < 8; m++) {
            const int k = kb + 2 * m;
            *(unsigned*)(bhp + xc * 272 + k * 2) = xh[m];
            *(unsigned*)(blp + xc * 272 + k * 2) = xl[m];
        }
        if (tt + 1 < nt && tid < 64) {
            const int c  = (t0 + tt + 1) * 64 + tid;
            const int cc = c < ncols ? c : ncols - 1;
            const int b  = cc / span;
            coloff[(cur ^ 1) * 64 + tid] = b * XB_STRIDE + l * l + (cc - b * span);
        }
        __syncthreads();

        // --- prefetch + convert X(t+1) (overlaps MMA below) ---
        if (tt + 1 < nt) {
            const float* xp = x + coloff[(cur ^ 1) * 64 + xc];
#pragma unroll
            for (int m = 0; m < 8; m++) {
                const float v0 = xp[(kb + 2 * m) * P_TOT];
                const float v1 = xp[(kb + 2 * m + 1) * P_TOT];
                const __nv_bfloat16 h0 = __float2bfloat16_rn(v0);
                const __nv_bfloat16 h1 = __float2bfloat16_rn(v1);
                const __nv_bfloat16 l0 = __float2bfloat16_rn(v0 - __bfloat162float(h0));
                const __nv_bfloat16 l1 = __float2bfloat16_rn(v1 - __bfloat162float(h1));
                xh[m] = ((unsigned)__bfloat16_as_ushort(h1) << 16) | __bfloat16_as_ushort(h0);
                xl[m] = ((unsigned)__bfloat16_as_ushort(l1) << 16) | __bfloat16_as_ushort(l0);
            }
        }

        // --- MMA: 8 k-steps x (4 nq x 3 terms) ---
        float acc[4][4];
#pragma unroll
        for (int nq = 0; nq < 4; nq++)
#pragma unroll
            for (int j = 0; j < 4; j++) acc[nq][j] = 0.0f;

#pragma unroll
        for (int ks = 0; ks < 8; ks++) {
            const unsigned ko = (unsigned)ks * 32u;
            unsigned ah[4], al[4], bh0[4], bh1[4], bl0[4], bl1[4];
            LDSM4(ah, aH0 + ko);   LDSM4(al, aL0 + ko);
            LDSM4(bh0, bH0 + ko);  LDSM4(bh1, bH1 + ko);
            LDSM4(bl0, bL0 + ko);  LDSM4(bl1, bL1 + ko);
#pragma unroll
            for (int nq = 0; nq < 4; nq++) {
                const unsigned* bph = (nq < 2) ? &bh0[(nq & 1) * 2] : &bh1[(nq & 1) * 2];
                const unsigned* bpl = (nq < 2) ? &bl0[(nq & 1) * 2] : &bl1[(nq & 1) * 2];
                MMA16816(acc[nq], ah, bph[0], bph[1]);  // Whi*Xhi
                MMA16816(acc[nq], ah, bpl[0], bpl[1]);  // Whi*Xlo
                MMA16816(acc[nq], al, bph[0], bph[1]);  // Wlo*Xhi
            }
        }

        // --- epilogue: guarded direct stores ---
        const int c0t = (t0 + tt) * 64;
        const int r   = m_base + (lane >> 2);
#pragma unroll
        for (int nq = 0; nq < 4; nq++) {
            const int cc = n_base + nq * 8 + (lane & 3) * 2;
            if (c0t + cc < ncols) {
                const int off = coloff[cur * 64 + cc];
                out[off + r * P_TOT]       = acc[nq][0];
                out[off + (r + 8) * P_TOT] = acc[nq][2];
            }
            if (c0t + cc + 1 < ncols) {
                const int off = coloff[cur * 64 + cc + 1];
                out[off + r * P_TOT]       = acc[nq][1];
                out[off + (r + 8) * P_TOT] = acc[nq][3];
            }
        }
        __syncthreads();
    }
}

extern "C" void kernel_launch(void* const* d_in, const int* in_sizes, int n_in,
                              void* d_out, int out_size)
{
    const float* x = (const float*)d_in[0];      // [16,128,6561]
    const float* w = (const float*)d_in[1];      // [128,128,17,1]
    float* out = (float*)d_out;                  // [16,128,6561]

    cudaFuncSetAttribute(shconv_mma,
                         cudaFuncAttributeMaxDynamicSharedMemorySize, DSMEM);

    shconv_interp_pack<<<512, 256>>>(w);

    dim3 grid(21, NDEG);                         // 2-tile chunks x degrees
    shconv_mma<<<grid, 512, DSMEM>>>(x, out);
}

// round 7
// speedup vs baseline: 2.2521x; 1.0137x over previous
#include <cuda_runtime.h>
#include <cuda_bf16.h>
#include <cstdint>

#define IN_CH   128
#define OUT_CH  128
#define NDEG    81
#define NCPT    17
#define P_TOT   6561
#define XB_STRIDE (IN_CH * P_TOT)

#define WROW 136                 // padded k-row length in bf16 (272 bytes)
#define WBLK (128 * WROW)        // per-degree elems (34816 B)
#define NT   3                   // 64-col tiles per CTA -> 588 CTAs = 2 waves

__device__ __align__(16) __nv_bfloat16 wA_hi[NDEG * WBLK];
__device__ __align__(16) __nv_bfloat16 wA_lo[NDEG * WBLK];

__device__ __forceinline__ unsigned smem_u32(const void* p) {
    unsigned a;
    asm("{ .reg .u64 t; cvta.to.shared.u64 t, %1; cvt.u32.u64 %0, t; }"
        : "=r"(a) : "l"(p));
    return a;
}

#define LDSM4(R, ADDR)                                                        \
    asm volatile("ldmatrix.sync.aligned.m8n8.x4.shared.b16 "                  \
                 "{%0,%1,%2,%3}, [%4];"                                       \
                 : "=r"((R)[0]), "=r"((R)[1]), "=r"((R)[2]), "=r"((R)[3])     \
                 : "r"(ADDR))

#define MMA16816(D, A, B0, B1)                                                \
    asm volatile("mma.sync.aligned.m16n8k16.row.col.f32.bf16.bf16.f32 "       \
                 "{%0,%1,%2,%3},{%4,%5,%6,%7},{%8,%9},{%0,%1,%2,%3};"         \
                 : "+f"((D)[0]), "+f"((D)[1]), "+f"((D)[2]), "+f"((D)[3])     \
                 : "r"((A)[0]), "r"((A)[1]), "r"((A)[2]), "r"((A)[3]),        \
                   "r"(B0), "r"(B1))

#define CPA16(DST, SRC)                                                       \
    asm volatile("cp.async.cg.shared.global [%0], [%1], 16;"                  \
                 :: "r"(DST), "l"(SRC))

// ---------------------------------------------------------------------------
// Kernel 1: interp + pack (unchanged — each anchor read once).
// ---------------------------------------------------------------------------
__global__ __launch_bounds__(256) void shconv_interp_pack(const float* __restrict__ w)
{
    __shared__ float anch[32][NCPT];
    const int o  = blockIdx.x >> 2;
    const int k0 = (blockIdx.x & 3) * 32;

    for (int e = threadIdx.x; e < 32 * NCPT; e += 256) {
        const int kk = e / NCPT, s = e % NCPT;
        anch[kk][s] = w[((k0 + kk) * OUT_CH + o) * NCPT + s];
    }
    __syncthreads();

    for (int e = threadIdx.x; e < NDEG * 32; e += 256) {
        const int l  = e >> 5;
        const int kk = e & 31;
        int s; float t;
        if (l < 75) { s = l / 5; t = (float)(l - s * 5) * 0.2f; }
        else        { s = 15;    t = (float)(l - 75) * 0.2f; }
        const float v = (1.0f - t) * anch[kk][s] + t * anch[kk][s + 1];
        const __nv_bfloat16 h  = __float2bfloat16_rn(v);
        const __nv_bfloat16 lo = __float2bfloat16_rn(v - __bfloat162float(h));
        const int idx = l * WBLK + o * WROW + k0 + kk;
        wA_hi[idx] = h;
        wA_lo[idx] = lo;
    }
}

// ---------------------------------------------------------------------------
// Kernel 2: 512-thread pipelined bf16 HMMA GEMM, warp-tile 16x32, NT=3.
//   D[128 o][64 c] = Whi*Xhi + Wlo*Xhi + Whi*Xlo   (fp32 accum)
// Term-major MMA ordering (acc reuse distance 4). Round-5 loop structure:
// epilogue BEFORE end-of-loop barrier (only 2 coloff generations live).
// ---------------------------------------------------------------------------
#define SM_AHI  0
#define SM_ALO  34816
#define SM_BHI  69632
#define SM_BLO  87040
#define SM_COL  104448
#define DSMEM   104960

__global__ __launch_bounds__(512, 2) void shconv_mma(const float* __restrict__ x,
                                                     float* __restrict__ out)
{
    const int l      = 80 - blockIdx.y;          // LPT: big degrees first
    const int ntiles = (l >> 1) + 1;
    const int t0     = blockIdx.x * NT;
    int nt = ntiles - t0;
    if (nt <= 0) return;
    if (nt > NT) nt = NT;

    extern __shared__ __align__(16) char sm[];
    int* coloff = (int*)(sm + SM_COL);
    const unsigned sb = smem_u32(sm);

    const int tid  = threadIdx.x;
    const int lane = tid & 31;
    const int wid  = tid >> 5;
    const int span  = 2 * l + 1;
    const int ncols = 16 * span;

    // --- W: cp.async both hi/lo blocks (2x2176 uint4) ---
    {
        const char* gh = (const char*)(wA_hi + l * WBLK);
        const char* gl = (const char*)(wA_lo + l * WBLK);
#pragma unroll
        for (int j = 0; j < 5; j++) {
            const int e = tid + 512 * j;
            if (e < 2176) {
                CPA16(sb + SM_AHI + e * 16, gh + e * 16);
                CPA16(sb + SM_ALO + e * 16, gl + e * 16);
            }
        }
        asm volatile("cp.async.commit_group;" ::: "memory");
    }

    // --- coloff for tile 0 (buffer 0) ---
    if (tid < 64) {
        const int c  = t0 * 64 + tid;
        const int cc = c < ncols ? c : ncols - 1;
        const int b  = cc / span;
        coloff[tid] = b * XB_STRIDE + l * l + (cc - b * span);
    }
    __syncthreads();

    // --- X ownership: thread -> (col xc, k in [kb, kb+16)), eager bf16 split ---
    const int xc = tid & 63;
    const int kb = (tid >> 6) * 16;
    unsigned xh[8], xl[8];
    {
        const float* xp = x + coloff[xc];
#pragma unroll
        for (int m = 0; m < 8; m++) {
            const float v0 = xp[(kb + 2 * m) * P_TOT];
            const float v1 = xp[(kb + 2 * m + 1) * P_TOT];
            const __nv_bfloat16 h0 = __float2bfloat16_rn(v0);
            const __nv_bfloat16 h1 = __float2bfloat16_rn(v1);
            const __nv_bfloat16 l0 = __float2bfloat16_rn(v0 - __bfloat162float(h0));
            const __nv_bfloat16 l1 = __float2bfloat16_rn(v1 - __bfloat162float(h1));
            xh[m] = ((unsigned)__bfloat16_as_ushort(h1) << 16) | __bfloat16_as_ushort(h0);
            xl[m] = ((unsigned)__bfloat16_as_ushort(l1) << 16) | __bfloat16_as_ushort(l0);
        }
    }
    asm volatile("cp.async.wait_group 0;" ::: "memory");

    // --- fragment addresses: warp-tile 16 (m) x 32 (n) ---
    const int m_base = (wid >> 1) * 16;
    const int n_base = (wid & 1) * 32;
    const unsigned aoff = (unsigned)(m_base + (lane & 15)) * 272u + (unsigned)(lane >> 4) * 16u;
    const unsigned aH0 = sb + SM_AHI + aoff;
    const unsigned aL0 = sb + SM_ALO + aoff;
    const unsigned boff = (unsigned)(n_base + ((lane & 7) | ((lane >> 4) << 3))) * 272u
                        + (unsigned)((lane >> 3) & 1) * 16u;
    const unsigned bH0 = sb + SM_BHI + boff, bH1 = bH0 + 16u * 272u;
    const unsigned bL0 = sb + SM_BLO + boff, bL1 = bL0 + 16u * 272u;

    char* bhp = sm + SM_BHI;
    char* blp = sm + SM_BLO;

    for (int tt = 0; tt < nt; tt++) {
        const int cur = tt & 1;

        // --- STS prefetched bf16 pairs ---
#pragma unroll
        for (int m = 0; m < 8; m++) {
            const int k = kb + 2 * m;
            *(unsigned*)(bhp + xc * 272 + k * 2) = xh[m];
            *(unsigned*)(blp + xc * 272 + k * 2) = xl[m];
        }
        if (tt + 1 < nt && tid < 64) {
            const int c  = (t0 + tt + 1) * 64 + tid;
            const int cc = c < ncols ? c : ncols - 1;
            const int b  = cc / span;
            coloff[(cur ^ 1) * 64 + tid] = b * XB_STRIDE + l * l + (cc - b * span);
        }
        __syncthreads();          // B(tt) + coloff(next) visible

        // --- prefetch + convert X(t+1) (overlaps MMA below) ---
        if (tt + 1 < nt) {
            const float* xp = x + coloff[(cur ^ 1) * 64 + xc];
#pragma unroll
            for (int m = 0; m < 8; m++) {
                const float v0 = xp[(kb + 2 * m) * P_TOT];
                const float v1 = xp[(kb + 2 * m + 1) * P_TOT];
                const __nv_bfloat16 h0 = __float2bfloat16_rn(v0);
                const __nv_bfloat16 h1 = __float2bfloat16_rn(v1);
                const __nv_bfloat16 l0 = __float2bfloat16_rn(v0 - __bfloat162float(h0));
                const __nv_bfloat16 l1 = __float2bfloat16_rn(v1 - __bfloat162float(h1));
                xh[m] = ((unsigned)__bfloat16_as_ushort(h1) << 16) | __bfloat16_as_ushort(h0);
                xl[m] = ((unsigned)__bfloat16_as_ushort(l1) << 16) | __bfloat16_as_ushort(l0);
            }
        }

        // --- MMA: 8 k-steps, TERM-MAJOR (acc reuse distance 4) ---
        float acc[4][4];
#pragma unroll
        for (int nq = 0; nq < 4; nq++)
#pragma unroll
            for (int j = 0; j < 4; j++) acc[nq][j] = 0.0f;

#pragma unroll
        for (int ks = 0; ks < 8; ks++) {
            const unsigned ko = (unsigned)ks * 32u;
            unsigned ah[4], al[4], bh0[4], bh1[4], bl0[4], bl1[4];
            LDSM4(ah, aH0 + ko);   LDSM4(bh0, bH0 + ko);  LDSM4(bh1, bH1 + ko);
            LDSM4(al, aL0 + ko);   LDSM4(bl0, bL0 + ko);  LDSM4(bl1, bL1 + ko);
            // term 1: Whi*Xhi
            MMA16816(acc[0], ah, bh0[0], bh0[1]);
            MMA16816(acc[1], ah, bh0[2], bh0[3]);
            MMA16816(acc[2], ah, bh1[0], bh1[1]);
            MMA16816(acc[3], ah, bh1[2], bh1[3]);
            // term 2: Wlo*Xhi
            MMA16816(acc[0], al, bh0[0], bh0[1]);
            MMA16816(acc[1], al, bh0[2], bh0[3]);
            MMA16816(acc[2], al, bh1[0], bh1[1]);
            MMA16816(acc[3], al, bh1[2], bh1[3]);
            // term 3: Whi*Xlo
            MMA16816(acc[0], ah, bl0[0], bl0[1]);
            MMA16816(acc[1], ah, bl0[2], bl0[3]);
            MMA16816(acc[2], ah, bl1[0], bl1[1]);
            MMA16816(acc[3], ah, bl1[2], bl1[3]);
        }

        // --- epilogue: guarded direct stores (before barrier — no races) ---
        const int c0t = (t0 + tt) * 64;
        const int r   = m_base + (lane >> 2);
#pragma unroll
        for (int nq = 0; nq < 4; nq++) {
            const int cc = n_base + nq * 8 + (lane & 3) * 2;
            if (c0t + cc < ncols) {
                const int off = coloff[cur * 64 + cc];
                out[off + r * P_TOT]       = acc[nq][0];
                out[off + (r + 8) * P_TOT] = acc[nq][2];
            }
            if (c0t + cc + 1 < ncols) {
                const int off = coloff[cur * 64 + cc + 1];
                out[off + r * P_TOT]       = acc[nq][1];
                out[off + (r + 8) * P_TOT] = acc[nq][3];
            }
        }
        __syncthreads();          // B + coloff(cur) free for reuse
    }
}

extern "C" void kernel_launch(void* const* d_in, const int* in_sizes, int n_in,
                              void* d_out, int out_size)
{
    const float* x = (const float*)d_in[0];      // [16,128,6561]
    const float* w = (const float*)d_in[1];      // [128,128,17,1]
    float* out = (float*)d_out;                  // [16,128,6561]

    cudaFuncSetAttribute(shconv_mma,
                         cudaFuncAttributeMaxDynamicSharedMemorySize, DSMEM);

    shconv_interp_pack<<<512, 256>>>(w);

    dim3 grid(14, NDEG);                         // 3-tile chunks x degrees
    shconv_mma<<<grid, 512, DSMEM>>>(x, out);
}

// round 8
// speedup vs baseline: 2.9607x; 1.3146x over previous
#include <cuda_runtime.h>
#include <cuda_fp16.h>
#include <cstdint>

#define IN_CH   128
#define OUT_CH  128
#define NDEG    81
#define NCPT    17
#define P_TOT   6561
#define XB_STRIDE (IN_CH * P_TOT)

#define WROW 136                 // padded k-row length in fp16 (272 bytes)
#define WBLK (128 * WROW)        // per-degree elems (34816 B)
#define NT   3                   // 64-col tiles per CTA -> 588 CTAs = 2 waves

__device__ __align__(16) __half wA[NDEG * WBLK];

__device__ __forceinline__ unsigned smem_u32(const void* p) {
    unsigned a;
    asm("{ .reg .u64 t; cvta.to.shared.u64 t, %1; cvt.u32.u64 %0, t; }"
        : "=r"(a) : "l"(p));
    return a;
}

#define LDSM4(R, ADDR)                                                        \
    asm volatile("ldmatrix.sync.aligned.m8n8.x4.shared.b16 "                  \
                 "{%0,%1,%2,%3}, [%4];"                                       \
                 : "=r"((R)[0]), "=r"((R)[1]), "=r"((R)[2]), "=r"((R)[3])     \
                 : "r"(ADDR))

#define MMA16816(D, A, B0, B1)                                                \
    asm volatile("mma.sync.aligned.m16n8k16.row.col.f32.f16.f16.f32 "         \
                 "{%0,%1,%2,%3},{%4,%5,%6,%7},{%8,%9},{%0,%1,%2,%3};"         \
                 : "+f"((D)[0]), "+f"((D)[1]), "+f"((D)[2]), "+f"((D)[3])     \
                 : "r"((A)[0]), "r"((A)[1]), "r"((A)[2]), "r"((A)[3]),        \
                   "r"(B0), "r"(B1))

#define CPA16(DST, SRC)                                                       \
    asm volatile("cp.async.cg.shared.global [%0], [%1], 16;"                  \
                 :: "r"(DST), "l"(SRC))

// ---------------------------------------------------------------------------
// Kernel 1: interp + pack -> fp16 W in padded [o][k] layout.
// ---------------------------------------------------------------------------
__global__ __launch_bounds__(256) void shconv_interp_pack(const float* __restrict__ w)
{
    __shared__ float anch[32][NCPT];
    const int o  = blockIdx.x >> 2;
    const int k0 = (blockIdx.x & 3) * 32;

    for (int e = threadIdx.x; e < 32 * NCPT; e += 256) {
        const int kk = e / NCPT, s = e % NCPT;
        anch[kk][s] = w[((k0 + kk) * OUT_CH + o) * NCPT + s];
    }
    __syncthreads();

    for (int e = threadIdx.x; e < NDEG * 32; e += 256) {
        const int l  = e >> 5;
        const int kk = e & 31;
        int s; float t;
        if (l < 75) { s = l / 5; t = (float)(l - s * 5) * 0.2f; }
        else        { s = 15;    t = (float)(l - 75) * 0.2f; }
        const float v = (1.0f - t) * anch[kk][s] + t * anch[kk][s + 1];
        wA[l * WBLK + o * WROW + k0 + kk] = __float2half_rn(v);
    }
}

// ---------------------------------------------------------------------------
// Kernel 2: 512-thread pipelined fp16 HMMA GEMM, warp-tile 16x32, NT=3.
//   D[128 o][64 c] = W * X    (fp16 inputs, fp32 accum)
// smem: W 34816 | B 17408 | coloff[2][64]
// ---------------------------------------------------------------------------
#define SM_W    0
#define SM_B    34816
#define SM_COL  52224
#define DSMEM   52736

__global__ __launch_bounds__(512, 2) void shconv_mma(const float* __restrict__ x,
                                                     float* __restrict__ out)
{
    const int l      = 80 - blockIdx.y;          // LPT: big degrees first
    const int ntiles = (l >> 1) + 1;
    const int t0     = blockIdx.x * NT;
    int nt = ntiles - t0;
    if (nt <= 0) return;
    if (nt > NT) nt = NT;

    extern __shared__ __align__(16) char sm[];
    int* coloff = (int*)(sm + SM_COL);
    const unsigned sb = smem_u32(sm);

    const int tid  = threadIdx.x;
    const int lane = tid & 31;
    const int wid  = tid >> 5;
    const int span  = 2 * l + 1;
    const int ncols = 16 * span;

    // --- W: cp.async (2176 uint4) ---
    {
        const char* gw = (const char*)(wA + l * WBLK);
#pragma unroll
        for (int j = 0; j < 5; j++) {
            const int e = tid + 512 * j;
            if (e < 2176)
                CPA16(sb + SM_W + e * 16, gw + e * 16);
        }
        asm volatile("cp.async.commit_group;" ::: "memory");
    }

    // --- coloff for tile 0 (buffer 0) ---
    if (tid < 64) {
        const int c  = t0 * 64 + tid;
        const int cc = c < ncols ? c : ncols - 1;
        const int b  = cc / span;
        coloff[tid] = b * XB_STRIDE + l * l + (cc - b * span);
    }
    __syncthreads();

    // --- X ownership: thread -> (col xc, k in [kb,kb+16)), eager fp16 pack ---
    const int xc = tid & 63;
    const int kb = (tid >> 6) * 16;
    unsigned xh[8];
    {
        const float* xp = x + coloff[xc];
#pragma unroll
        for (int m = 0; m < 8; m++) {
            const __half h0 = __float2half_rn(xp[(kb + 2 * m) * P_TOT]);
            const __half h1 = __float2half_rn(xp[(kb + 2 * m + 1) * P_TOT]);
            xh[m] = ((unsigned)__half_as_ushort(h1) << 16) | __half_as_ushort(h0);
        }
    }
    asm volatile("cp.async.wait_group 0;" ::: "memory");

    // --- fragment addresses: warp-tile 16 (m) x 32 (n) ---
    const int m_base = (wid >> 1) * 16;
    const int n_base = (wid & 1) * 32;
    const unsigned aoff = (unsigned)(m_base + (lane & 15)) * 272u + (unsigned)(lane >> 4) * 16u;
    const unsigned aW = sb + SM_W + aoff;
    const unsigned boff = (unsigned)(n_base + ((lane & 7) | ((lane >> 4) << 3))) * 272u
                        + (unsigned)((lane >> 3) & 1) * 16u;
    const unsigned bB0 = sb + SM_B + boff, bB1 = bB0 + 16u * 272u;

    char* bp = sm + SM_B;

    for (int tt = 0; tt < nt; tt++) {
        const int cur = tt & 1;

        // --- STS prefetched fp16: 32B contiguous -> two 16B vector stores ---
        {
            uint4 v0 = { xh[0], xh[1], xh[2], xh[3] };
            uint4 v1 = { xh[4], xh[5], xh[6], xh[7] };
            *(uint4*)(bp + xc * 272 + kb * 2)      = v0;
            *(uint4*)(bp + xc * 272 + kb * 2 + 16) = v1;
        }
        if (tt + 1 < nt && tid < 64) {
            const int c  = (t0 + tt + 1) * 64 + tid;
            const int cc = c < ncols ? c : ncols - 1;
            const int b  = cc / span;
            coloff[(cur ^ 1) * 64 + tid] = b * XB_STRIDE + l * l + (cc - b * span);
        }
        __syncthreads();          // B(tt) + coloff(next) visible

        // --- prefetch + convert X(t+1) (overlaps MMA below) ---
        if (tt + 1 < nt) {
            const float* xp = x + coloff[(cur ^ 1) * 64 + xc];
#pragma unroll
            for (int m = 0; m < 8; m++) {
                const __half h0 = __float2half_rn(xp[(kb + 2 * m) * P_TOT]);
                const __half h1 = __float2half_rn(xp[(kb + 2 * m + 1) * P_TOT]);
                xh[m] = ((unsigned)__half_as_ushort(h1) << 16) | __half_as_ushort(h0);
            }
        }

        // --- MMA: 8 k-steps x 4 nq ---
        float acc[4][4];
#pragma unroll
        for (int nq = 0; nq < 4; nq++)
#pragma unroll
            for (int j = 0; j < 4; j++) acc[nq][j] = 0.0f;

#pragma unroll
        for (int ks = 0; ks < 8; ks++) {
            const unsigned ko = (unsigned)ks * 32u;
            unsigned ah[4], b0[4], b1[4];
            LDSM4(ah, aW + ko);
            LDSM4(b0, bB0 + ko);
            LDSM4(b1, bB1 + ko);
            MMA16816(acc[0], ah, b0[0], b0[1]);
            MMA16816(acc[1], ah, b0[2], b0[3]);
            MMA16816(acc[2], ah, b1[0], b1[1]);
            MMA16816(acc[3], ah, b1[2], b1[3]);
        }

        // --- epilogue: guarded direct stores (before barrier) ---
        const int c0t = (t0 + tt) * 64;
        const int r   = m_base + (lane >> 2);
#pragma unroll
        for (int nq = 0; nq < 4; nq++) {
            const int cc = n_base + nq * 8 + (lane & 3) * 2;
            if (c0t + cc < ncols) {
                const int off = coloff[cur * 64 + cc];
                out[off + r * P_TOT]       = acc[nq][0];
                out[off + (r + 8) * P_TOT] = acc[nq][2];
            }
            if (c0t + cc + 1 < ncols) {
                const int off = coloff[cur * 64 + cc + 1];
                out[off + r * P_TOT]       = acc[nq][1];
                out[off + (r + 8) * P_TOT] = acc[nq][3];
            }
        }
        __syncthreads();          // B + coloff(cur) free for reuse
    }
}

extern "C" void kernel_launch(void* const* d_in, const int* in_sizes, int n_in,
                              void* d_out, int out_size)
{
    const float* x = (const float*)d_in[0];      // [16,128,6561]
    const float* w = (const float*)d_in[1];      // [128,128,17,1]
    float* out = (float*)d_out;                  // [16,128,6561]

    cudaFuncSetAttribute(shconv_mma,
                         cudaFuncAttributeMaxDynamicSharedMemorySize, DSMEM);

    shconv_interp_pack<<<512, 256>>>(w);

    dim3 grid(14, NDEG);                         // 3-tile chunks x degrees
    shconv_mma<<<grid, 512, DSMEM>>>(x, out);
}